// round 2
// baseline (speedup 1.0000x reference)
#include <cuda_runtime.h>
#include <math.h>

#define NG 8
#define LG 1024
#define NH 8
#define HD 16
#define DS 64
#define NB 64          // NG*NH batches
#define NE 131072      // total edges
#define NN_NODES 8192  // NG*LG

// ---------------- scratch (static device globals; no allocations) ----------------
__device__ float g_S [64ULL*1024*1024];   // scatter target A[b,h,sl,dl]; reused as ping buffer
__device__ float g_P0[64ULL*1024*1024];   // M / ping buffer
__device__ float g_O0[64ULL*1024*1024];   // out ping
__device__ float g_O1[64ULL*1024*1024];   // out pong
__device__ float g_G [8ULL*1024*1024];    // G[b,l,t]
__device__ float g_e0[NH*NN_NODES];
__device__ float g_e1[NH*NN_NODES];
__device__ float g_dummy[NH*NN_NODES];
__device__ float g_w[NH*NN_NODES];        // dt_self, layout [h][n]
__device__ float g_nrm[NB*LG];            // 1/(rowsum + dummy + TOL)

__device__ __forceinline__ float softplusf(float x) {
    return (x > 15.f) ? x : log1pf(expf(x));
}

// ---------------- 1) zero the scatter buffer ----------------
__global__ void k_zero(float* __restrict__ p, size_t n) {
    size_t i = ((size_t)blockIdx.x * blockDim.x + threadIdx.x) * 4;
    size_t stride = (size_t)gridDim.x * blockDim.x * 4;
    float4 z = make_float4(0.f, 0.f, 0.f, 0.f);
    for (; i < n; i += stride) *(float4*)(p + i) = z;
}

// ---------------- 2) per-node prep ----------------
__global__ void k_node(const float* __restrict__ dt, const float* __restrict__ dt_bias) {
    int i = blockIdx.x * blockDim.x + threadIdx.x;
    if (i >= NN_NODES * NH) return;
    int n = i >> 3, h = i & 7;
    float b = dt_bias[h];
    const float* row = dt + (size_t)n * (NH * 4) + h * 4;
    g_e0   [h * NN_NODES + n] = -softplusf(row[0] + b);
    g_e1   [h * NN_NODES + n] = -softplusf(row[1] + b);
    g_dummy[h * NN_NODES + n] = expf(-softplusf(row[2] + b));
    g_w    [h * NN_NODES + n] = row[3];          // raw dt_self (no transform)
}

// ---------------- 3) edge scatter ----------------
__global__ void k_scatter(const int* __restrict__ ei) {
    int idx = blockIdx.x * blockDim.x + threadIdx.x;
    if (idx >= NE * NH) return;
    int e = idx >> 3, h = idx & 7;
    int s = ei[e], d = ei[NE + e];
    int b = s >> 10, sl = s & 1023, dl = d & 1023;
    float v = expf(0.5f * (g_e0[h * NN_NODES + s] + g_e1[h * NN_NODES + d]));
    atomicAdd(&g_S[(((size_t)(b * NH + h)) * LG + sl) * LG + dl], v);
}

// ---------------- 4a) row sums -> reciprocal normalizer ----------------
__global__ void k_norm() {
    int r = blockIdx.x * 8 + (threadIdx.x >> 5);   // global row in [0, NB*LG)
    int lane = threadIdx.x & 31;
    const float* row = g_S + (size_t)r * LG;
    float s = 0.f;
    for (int j = lane; j < LG; j += 32) s += row[j];
    #pragma unroll
    for (int o = 16; o; o >>= 1) s += __shfl_xor_sync(0xFFFFFFFFu, s, o);
    if (lane == 0) {
        int bh = r >> 10, l = r & 1023;
        int b = bh >> 3, h = bh & 7;
        g_nrm[r] = 1.f / (s + g_dummy[h * NN_NODES + b * LG + l] + 0.1f);
    }
}

// ---------------- 4b) M = A_norm^T ; O = I + M ----------------
__global__ void k_transpose() {
    __shared__ float t[32][33];
    int bh = blockIdx.z;
    int i0 = blockIdx.x * 32, j0 = blockIdx.y * 32;
    size_t off = (size_t)bh * LG * LG;
    const float* S = g_S + off;
    float* M = g_P0 + off;
    float* O = g_O0 + off;
    int tx = threadIdx.x, ty = threadIdx.y;     // (32, 8)
    #pragma unroll
    for (int k = 0; k < 4; k++) {
        int j = j0 + ty + k * 8;
        t[ty + k * 8][tx] = S[(size_t)j * LG + i0 + tx];
    }
    __syncthreads();
    #pragma unroll
    for (int k = 0; k < 4; k++) {
        int i = i0 + ty + k * 8;
        int j = j0 + tx;
        float v = t[tx][ty + k * 8] * g_nrm[bh * LG + j];
        M[(size_t)i * LG + j] = v;
        O[(size_t)i * LG + j] = v + (i == j ? 1.f : 0.f);
    }
}

// ---------------- 5) batched 1024x1024x1024 SGEMM: C = A@B (+Cadd) ----------------
__global__ void __launch_bounds__(256) k_sgemm(const float* __restrict__ A,
                                               const float* __restrict__ B,
                                               float* __restrict__ C,
                                               const float* __restrict__ Cadd) {
    const int L = 1024;
    size_t off = (size_t)blockIdx.z * L * L;
    A += off; B += off; C += off;
    if (Cadd) Cadd += off;

    __shared__ float As[16][64];
    __shared__ float Bs[16][64];

    int tid = threadIdx.x;
    int tx = tid & 15, ty = tid >> 4;
    int row0 = blockIdx.y * 64, col0 = blockIdx.x * 64;

    int aRow = tid >> 2,  aC4 = (tid & 3) << 2;
    int bRow = tid >> 4,  bC4 = (tid & 15) << 2;

    float acc[4][4] = {};

    for (int kt = 0; kt < 64; kt++) {
        float4 av = *(const float4*)(A + (size_t)(row0 + aRow) * L + kt * 16 + aC4);
        As[aC4 + 0][aRow] = av.x;
        As[aC4 + 1][aRow] = av.y;
        As[aC4 + 2][aRow] = av.z;
        As[aC4 + 3][aRow] = av.w;
        *(float4*)&Bs[bRow][bC4] =
            *(const float4*)(B + (size_t)(kt * 16 + bRow) * L + col0 + bC4);
        __syncthreads();
        #pragma unroll
        for (int k = 0; k < 16; k++) {
            float4 a = *(const float4*)&As[k][ty * 4];
            float4 b = *(const float4*)&Bs[k][tx * 4];
            acc[0][0] += a.x * b.x; acc[0][1] += a.x * b.y; acc[0][2] += a.x * b.z; acc[0][3] += a.x * b.w;
            acc[1][0] += a.y * b.x; acc[1][1] += a.y * b.y; acc[1][2] += a.y * b.z; acc[1][3] += a.y * b.w;
            acc[2][0] += a.z * b.x; acc[2][1] += a.z * b.y; acc[2][2] += a.z * b.z; acc[2][3] += a.z * b.w;
            acc[3][0] += a.w * b.x; acc[3][1] += a.w * b.y; acc[3][2] += a.w * b.z; acc[3][3] += a.w * b.w;
        }
        __syncthreads();
    }

    #pragma unroll
    for (int i = 0; i < 4; i++) {
        int r = row0 + ty * 4 + i;
        float4 addv = Cadd ? *(const float4*)(Cadd + (size_t)r * L + col0 + tx * 4)
                           : make_float4(0.f, 0.f, 0.f, 0.f);
        float4 o;
        o.x = acc[i][0] + addv.x;
        o.y = acc[i][1] + addv.y;
        o.z = acc[i][2] + addv.z;
        o.w = acc[i][3] + addv.w;
        *(float4*)(C + (size_t)r * L + col0 + tx * 4) = o;
    }
}

// ---------------- 6) G[b,l,t] = sum_d C[b,l,d] * B[b,t,d] ----------------
__global__ void __launch_bounds__(256) k_gmat(const float* __restrict__ Cm,
                                              const float* __restrict__ Bm) {
    __shared__ float Cs[64][65];
    __shared__ float Bs2[64][65];
    int b = blockIdx.z;
    int t0 = blockIdx.x * 64, l0 = blockIdx.y * 64;
    int tid = threadIdx.x;
    #pragma unroll
    for (int q = 0; q < 4; q++) {
        int idx = tid + q * 256;
        int r = idx >> 4, c4 = (idx & 15) * 4;
        float4 v = *(const float4*)(Cm + ((size_t)(b * LG + l0 + r)) * DS + c4);
        Cs[r][c4] = v.x; Cs[r][c4 + 1] = v.y; Cs[r][c4 + 2] = v.z; Cs[r][c4 + 3] = v.w;
        float4 w = *(const float4*)(Bm + ((size_t)(b * LG + t0 + r)) * DS + c4);
        Bs2[r][c4] = w.x; Bs2[r][c4 + 1] = w.y; Bs2[r][c4 + 2] = w.z; Bs2[r][c4 + 3] = w.w;
    }
    __syncthreads();
    int tx = tid & 15, ty = tid >> 4;
    float acc[4][4] = {};
    for (int d = 0; d < 64; d++) {
        float c[4], bb[4];
        #pragma unroll
        for (int i = 0; i < 4; i++) c[i]  = Cs[ty * 4 + i][d];
        #pragma unroll
        for (int j = 0; j < 4; j++) bb[j] = Bs2[tx * 4 + j][d];
        #pragma unroll
        for (int i = 0; i < 4; i++)
            #pragma unroll
            for (int j = 0; j < 4; j++)
                acc[i][j] += c[i] * bb[j];
    }
    #pragma unroll
    for (int i = 0; i < 4; i++)
        #pragma unroll
        for (int j = 0; j < 4; j++)
            g_G[((size_t)b * LG + l0 + ty * 4 + i) * LG + t0 + tx * 4 + j] = acc[i][j];
}

// ---------------- 7) y = ((Lmat . G) * dt_self_t) @ x_head + x ----------------
__global__ void __launch_bounds__(256) k_final(const float* __restrict__ O,
                                               const float* __restrict__ x,
                                               const float* __restrict__ Dp,
                                               float* __restrict__ out) {
    int bh = blockIdx.z;
    int b = bh >> 3, h = bh & 7;
    int l0 = blockIdx.x * 64;
    const float* Ob = O   + (size_t)bh * LG * LG;
    const float* Gb = g_G + (size_t)b  * LG * LG;

    __shared__ float Os[64][65];
    __shared__ float Gs[64][65];
    __shared__ float xs[64][17];
    __shared__ float ws[64];

    int tid = threadIdx.x;
    int l = tid & 63;
    int d0 = (tid >> 6) * 4;
    float acc[4] = {0.f, 0.f, 0.f, 0.f};

    for (int t0 = 0; t0 < LG; t0 += 64) {
        #pragma unroll
        for (int q = 0; q < 4; q++) {
            int idx = tid + q * 256;
            int r = idx >> 4, c4 = (idx & 15) * 4;
            float4 v = *(const float4*)(Ob + (size_t)(l0 + r) * LG + t0 + c4);
            Os[r][c4] = v.x; Os[r][c4 + 1] = v.y; Os[r][c4 + 2] = v.z; Os[r][c4 + 3] = v.w;
            float4 g = *(const float4*)(Gb + (size_t)(l0 + r) * LG + t0 + c4);
            Gs[r][c4] = g.x; Gs[r][c4 + 1] = g.y; Gs[r][c4 + 2] = g.z; Gs[r][c4 + 3] = g.w;
        }
        {
            int t = tid >> 2, d4 = (tid & 3) * 4;
            float4 v = *(const float4*)(x + (size_t)(b * LG + t0 + t) * 128 + h * HD + d4);
            xs[t][d4] = v.x; xs[t][d4 + 1] = v.y; xs[t][d4 + 2] = v.z; xs[t][d4 + 3] = v.w;
        }
        if (tid < 64) ws[tid] = g_w[h * NN_NODES + b * LG + t0 + tid];
        __syncthreads();
        #pragma unroll 8
        for (int tt = 0; tt < 64; tt++) {
            float a = Os[l][tt] * Gs[l][tt] * ws[tt];
            #pragma unroll
            for (int j = 0; j < 4; j++) acc[j] += a * xs[tt][d0 + j];
        }
        __syncthreads();
    }

    float dh = Dp[h];
    int n = b * LG + l0 + l;
    #pragma unroll
    for (int j = 0; j < 4; j++) {
        float xv = x[(size_t)n * 128 + h * HD + d0 + j];
        out[(size_t)n * 128 + (d0 + j) * NH + h] = acc[j] + xv * dh;   // out[n, d*8+h]
    }
}

// ---------------- host launcher ----------------
extern "C" void kernel_launch(void* const* d_in, const int* in_sizes, int n_in,
                              void* d_out, int out_size) {
    const float* x   = (const float*)d_in[0];
    const float* Bm  = (const float*)d_in[1];
    const float* Cm  = (const float*)d_in[2];
    const float* dt  = (const float*)d_in[3];
    const float* dtb = (const float*)d_in[4];
    const float* Dp  = (const float*)d_in[5];
    const int*   ei  = (const int*)  d_in[6];
    float* out = (float*)d_out;

    float *S, *P0, *O0, *O1;
    cudaGetSymbolAddress((void**)&S,  g_S);
    cudaGetSymbolAddress((void**)&P0, g_P0);
    cudaGetSymbolAddress((void**)&O0, g_O0);
    cudaGetSymbolAddress((void**)&O1, g_O1);

    size_t NNf = 64ULL * 1024 * 1024;
    k_zero<<<2048, 256>>>(S, NNf);
    k_node<<<(NN_NODES * NH + 255) / 256, 256>>>(dt, dtb);
    k_scatter<<<(NE * NH) / 256, 256>>>(ei);
    k_norm<<<(NB * LG) / 8, 256>>>();
    k_transpose<<<dim3(32, 32, NB), dim3(32, 8)>>>();

    dim3 mg(16, 16, NB), mb(256);
    float* Lc = P0; float* Ln = S;     // "last" ping-pong (M lives in P0; S free after transpose)
    float* Oc = O0; float* On = O1;    // "out" ping-pong
    for (int it = 0; it < 5; it++) {
        k_sgemm<<<mg, mb>>>(Lc, Lc, Ln, nullptr);  // last = last @ last
        k_sgemm<<<mg, mb>>>(Oc, Ln, On, Oc);       // out  = out + out @ last
        float* t;
        t = Lc; Lc = Ln; Ln = t;
        t = Oc; Oc = On; On = t;
    }

    k_gmat<<<dim3(16, 16, NG), 256>>>(Cm, Bm);
    k_final<<<dim3(16, 1, NB), 256>>>(Oc, x, Dp, out);
}

// round 4
// speedup vs baseline: 2.6747x; 2.6747x over previous
#include <cuda_runtime.h>
#include <cuda_bf16.h>
#include <stdint.h>
#include <math.h>

#define NG 8
#define LG 1024
#define NH 8
#define HD 16
#define DS 64
#define NB 64
#define NE 131072
#define NN_NODES 8192
#define MSZ (64ULL * 1024 * 1024)

__device__ float g_S[MSZ];
__device__ float g_G[8ULL * 1024 * 1024];
__device__ __nv_bfloat16 g_La_h[MSZ], g_La_l[MSZ], g_LaT_h[MSZ], g_LaT_l[MSZ];
__device__ __nv_bfloat16 g_Lb_h[MSZ], g_Lb_l[MSZ], g_LbT_h[MSZ], g_LbT_l[MSZ];
__device__ __nv_bfloat16 g_Oa_h[MSZ], g_Oa_l[MSZ], g_Ob_h[MSZ], g_Ob_l[MSZ];
__device__ float g_e0[NH * NN_NODES];
__device__ float g_e1[NH * NN_NODES];
__device__ float g_dummy[NH * NN_NODES];
__device__ float g_w[NH * NN_NODES];
__device__ float g_nrm[NB * LG];

// ---------------- helpers ----------------
__device__ __forceinline__ uint32_t smem_u32(const void* p) {
    uint32_t a;
    asm("{ .reg .u64 t; cvta.to.shared.u64 t, %1; cvt.u32.u64 %0, t; }" : "=r"(a) : "l"(p));
    return a;
}
#define CP16(dst, src) asm volatile("cp.async.cg.shared.global [%0], [%1], 16;" :: "r"(dst), "l"(src) : "memory")
#define CP_COMMIT()    asm volatile("cp.async.commit_group;" ::: "memory")
#define CP_WAIT1()     asm volatile("cp.async.wait_group 1;" ::: "memory")
#define CP_WAIT0()     asm volatile("cp.async.wait_group 0;" ::: "memory")

#define LDSM4(r, addr) \
    asm volatile("ldmatrix.sync.aligned.m8n8.x4.shared.b16 {%0,%1,%2,%3}, [%4];" \
        : "=r"((r)[0]), "=r"((r)[1]), "=r"((r)[2]), "=r"((r)[3]) : "r"(addr))

#define MMA16816(d, a, b0, b1) \
    asm volatile("mma.sync.aligned.m16n8k16.row.col.f32.bf16.bf16.f32 " \
        "{%0,%1,%2,%3}, {%4,%5,%6,%7}, {%8,%9}, {%0,%1,%2,%3};" \
        : "+f"((d)[0]), "+f"((d)[1]), "+f"((d)[2]), "+f"((d)[3]) \
        : "r"((a)[0]), "r"((a)[1]), "r"((a)[2]), "r"((a)[3]), "r"(b0), "r"(b1))

__device__ __forceinline__ float bf_lo(uint32_t u) { return __bfloat162float(__ushort_as_bfloat16((unsigned short)(u & 0xFFFF))); }
__device__ __forceinline__ float bf_hi(uint32_t u) { return __bfloat162float(__ushort_as_bfloat16((unsigned short)(u >> 16))); }
__device__ __forceinline__ void split_bf16(float v, __nv_bfloat16& h, __nv_bfloat16& l) {
    h = __float2bfloat16(v);
    l = __float2bfloat16(v - __bfloat162float(h));
}
__device__ __forceinline__ uint32_t pack2(__nv_bfloat16 a, __nv_bfloat16 b) {
    return ((uint32_t)__bfloat16_as_ushort(b) << 16) | __bfloat16_as_ushort(a);
}
__device__ __forceinline__ float softplusf(float x) { return (x > 15.f) ? x : log1pf(expf(x)); }

// ---------------- small kernels ----------------
__global__ void k_zero(float* __restrict__ p, size_t n) {
    size_t i = ((size_t)blockIdx.x * blockDim.x + threadIdx.x) * 4;
    size_t st = (size_t)gridDim.x * blockDim.x * 4;
    float4 z = make_float4(0.f, 0.f, 0.f, 0.f);
    for (; i < n; i += st) *(float4*)(p + i) = z;
}

__global__ void k_node(const float* __restrict__ dt, const float* __restrict__ dtb) {
    int i = blockIdx.x * blockDim.x + threadIdx.x;
    if (i >= NN_NODES * NH) return;
    int n = i >> 3, h = i & 7;
    float b = dtb[h];
    const float* row = dt + (size_t)n * (NH * 4) + h * 4;
    g_e0[h * NN_NODES + n] = -softplusf(row[0] + b);
    g_e1[h * NN_NODES + n] = -softplusf(row[1] + b);
    g_dummy[h * NN_NODES + n] = expf(-softplusf(row[2] + b));
    g_w[h * NN_NODES + n] = row[3];
}

__global__ void k_scatter(const int* __restrict__ ei) {
    int idx = blockIdx.x * blockDim.x + threadIdx.x;
    if (idx >= NE * NH) return;
    int e = idx >> 3, h = idx & 7;
    int s = ei[e], d = ei[NE + e];
    int b = s >> 10, sl = s & 1023, dl = d & 1023;
    float v = expf(0.5f * (g_e0[h * NN_NODES + s] + g_e1[h * NN_NODES + d]));
    atomicAdd(&g_S[(((size_t)(b * NH + h)) * LG + sl) * LG + dl], v);
}

__global__ void k_norm() {
    int r = blockIdx.x * 8 + (threadIdx.x >> 5);
    int lane = threadIdx.x & 31;
    const float* row = g_S + (size_t)r * LG;
    float s = 0.f;
    for (int j = lane; j < LG; j += 32) s += row[j];
    #pragma unroll
    for (int o = 16; o; o >>= 1) s += __shfl_xor_sync(0xFFFFFFFFu, s, o);
    if (lane == 0) {
        int bh = r >> 10, l = r & 1023;
        int b = bh >> 3, h = bh & 7;
        g_nrm[r] = 1.f / (s + g_dummy[h * NN_NODES + b * LG + l] + 0.1f);
    }
}

// M = A_norm^T -> La ; A_norm (=M^T) -> LaT ; O = I+M -> Oa  (split bf16)
__global__ void k_prep() {
    __shared__ float t[32][33];
    int bh = blockIdx.z;
    int i0 = blockIdx.x * 32, j0 = blockIdx.y * 32;
    size_t off = (size_t)bh << 20;
    int tx = threadIdx.x, ty = threadIdx.y;   // (32, 8)
    #pragma unroll
    for (int k = 0; k < 4; k++) {
        int j = j0 + ty + k * 8;
        float v = g_S[off + (size_t)j * LG + i0 + tx];
        t[ty + k * 8][tx] = v;
        float mt = v * g_nrm[bh * LG + j];
        size_t o = off + (size_t)j * LG + i0 + tx;
        __nv_bfloat16 h, l; split_bf16(mt, h, l);
        g_LaT_h[o] = h; g_LaT_l[o] = l;
    }
    __syncthreads();
    #pragma unroll
    for (int k = 0; k < 4; k++) {
        int i = i0 + ty + k * 8;
        int j = j0 + tx;
        float v = t[tx][ty + k * 8] * g_nrm[bh * LG + j];
        size_t o = off + (size_t)i * LG + j;
        __nv_bfloat16 h, l; split_bf16(v, h, l);
        g_La_h[o] = h; g_La_l[o] = l;
        float w = v + ((i == j) ? 1.f : 0.f);
        split_bf16(w, h, l);
        g_Oa_h[o] = h; g_Oa_l[o] = l;
    }
}

// split-bf16 batched transpose
__global__ void __launch_bounds__(256) k_tp(const __nv_bfloat16* __restrict__ ih,
                                            const __nv_bfloat16* __restrict__ il,
                                            __nv_bfloat16* __restrict__ oh,
                                            __nv_bfloat16* __restrict__ ol) {
    __shared__ __nv_bfloat16 th[64][66], tl[64][66];
    size_t off = (size_t)blockIdx.z << 20;
    int i0 = blockIdx.x * 64, j0 = blockIdx.y * 64;
    int tid = threadIdx.x;
    #pragma unroll
    for (int q = 0; q < 2; q++) {
        int idx = tid + q * 256;
        int r = idx >> 3, c8 = (idx & 7) * 8;
        uint4 vh = *(const uint4*)(ih + off + (size_t)(j0 + r) * LG + i0 + c8);
        uint4 vl = *(const uint4*)(il + off + (size_t)(j0 + r) * LG + i0 + c8);
        const uint32_t* ph = (const uint32_t*)&vh;
        const uint32_t* pl = (const uint32_t*)&vl;
        #pragma unroll
        for (int p = 0; p < 4; p++) {
            th[r][c8 + 2 * p]     = __ushort_as_bfloat16((unsigned short)(ph[p] & 0xFFFF));
            th[r][c8 + 2 * p + 1] = __ushort_as_bfloat16((unsigned short)(ph[p] >> 16));
            tl[r][c8 + 2 * p]     = __ushort_as_bfloat16((unsigned short)(pl[p] & 0xFFFF));
            tl[r][c8 + 2 * p + 1] = __ushort_as_bfloat16((unsigned short)(pl[p] >> 16));
        }
    }
    __syncthreads();
    #pragma unroll
    for (int q = 0; q < 8; q++) {
        int idx = tid + q * 256;
        int r = idx >> 5, c2 = (idx & 31) * 2;
        uint32_t vh = pack2(th[c2][r], th[c2 + 1][r]);
        uint32_t vl = pack2(tl[c2][r], tl[c2 + 1][r]);
        *(uint32_t*)(oh + off + (size_t)(i0 + r) * LG + j0 + c2) = vh;
        *(uint32_t*)(ol + off + (size_t)(i0 + r) * LG + j0 + c2) = vl;
    }
}

// ---------------- HMMA batched GEMM: C = A@B (+Add), split bf16 x3 ----------------
// A [M,K] row-major; B given as B^T [N,K] row-major. Tile 128x128, KC=32, 2 stages.
// SMEM per stage: Ah(0) Al(10240) Bh(20480) Bl(30720), row stride 80B. Stage stride 40960.
#define MMA_SMEM (2 * 40960)

__global__ void __launch_bounds__(256) k_mma(const __nv_bfloat16* __restrict__ Ah,
                                             const __nv_bfloat16* __restrict__ Al,
                                             const __nv_bfloat16* __restrict__ Bh,
                                             const __nv_bfloat16* __restrict__ Bl,
                                             __nv_bfloat16* __restrict__ Ch,
                                             __nv_bfloat16* __restrict__ Cl,
                                             const __nv_bfloat16* __restrict__ Addh,
                                             const __nv_bfloat16* __restrict__ Addl) {
    extern __shared__ __align__(16) char dsm[];
    size_t moff = (size_t)blockIdx.z << 20;
    Ah += moff; Al += moff; Bh += moff; Bl += moff; Ch += moff; Cl += moff;
    if (Addh) { Addh += moff; Addl += moff; }
    int row0 = blockIdx.y * 128, col0 = blockIdx.x * 128;

    uint32_t sm0 = smem_u32(dsm);
    int tid = threadIdx.x, wid = tid >> 5, lane = tid & 31;
    int wm = (wid >> 2) * 64, wn = (wid & 3) * 32;

    // accumulators: 4 m-tiles x 4 n-tiles x 4 fp32
    float acc[4][4][4];
    #pragma unroll
    for (int i = 0; i < 4; i++)
        #pragma unroll
        for (int j = 0; j < 4; j++)
            #pragma unroll
            for (int k = 0; k < 4; k++) acc[i][j][k] = 0.f;

    const int r_ld = tid >> 2, c_ld = (tid & 3);   // 64 rows x 4 chunks per 256-thread pass

    auto preload = [&](int kt, int s) {
        uint32_t base = sm0 + s * 40960;
        #pragma unroll
        for (int q = 0; q < 2; q++) {
            int r = r_ld + q * 64;
            uint32_t so = (uint32_t)(r * 80 + c_ld * 16);
            size_t go = (size_t)(row0 + r) * 1024 + kt * 32 + c_ld * 8;
            CP16(base + so,         (const char*)(Ah + go));
            CP16(base + 10240 + so, (const char*)(Al + go));
            size_t gb = (size_t)(col0 + r) * 1024 + kt * 32 + c_ld * 8;
            CP16(base + 20480 + so, (const char*)(Bh + gb));
            CP16(base + 30720 + so, (const char*)(Bl + gb));
        }
        CP_COMMIT();
    };

    preload(0, 0);

    for (int kt = 0; kt < 32; kt++) {
        int s = kt & 1;
        if (kt + 1 < 32) { preload(kt + 1, s ^ 1); CP_WAIT1(); }
        else             { CP_WAIT0(); }
        __syncthreads();

        uint32_t ab = sm0 + s * 40960;
        #pragma unroll
        for (int kh = 0; kh < 2; kh++) {
            int kb = kh * 32;   // byte offset of k16 half within 64B row
            uint32_t ah[4][4], al[4][4];
            #pragma unroll
            for (int mi = 0; mi < 4; mi++) {
                uint32_t ad = ab + (uint32_t)((wm + mi * 16 + (lane & 15)) * 80 + kb + (lane >> 4) * 16);
                LDSM4(ah[mi], ad);
                LDSM4(al[mi], ad + 10240);
            }
            uint32_t bhf[2][4], blf[2][4];
            #pragma unroll
            for (int nj = 0; nj < 2; nj++) {
                uint32_t bd = ab + 20480 + (uint32_t)((wn + nj * 16 + (lane & 15)) * 80 + kb + (lane >> 4) * 16);
                LDSM4(bhf[nj], bd);
                LDSM4(blf[nj], bd + 10240);
            }
            #pragma unroll
            for (int mi = 0; mi < 4; mi++) {
                #pragma unroll
                for (int ni = 0; ni < 4; ni++) {
                    int g = ni >> 1, w = ni & 1;
                    MMA16816(acc[mi][ni], ah[mi], bhf[g][w], bhf[g][2 + w]);   // Ah*Bh
                    MMA16816(acc[mi][ni], ah[mi], blf[g][w], blf[g][2 + w]);   // Ah*Bl
                    MMA16816(acc[mi][ni], al[mi], bhf[g][w], bhf[g][2 + w]);   // Al*Bh
                }
            }
        }
        __syncthreads();
    }

    // epilogue
    int rl = lane >> 2, cl = (lane & 3) * 2;
    #pragma unroll
    for (int mi = 0; mi < 4; mi++) {
        #pragma unroll
        for (int ni = 0; ni < 4; ni++) {
            size_t rA = (size_t)(row0 + wm + mi * 16 + rl) * 1024 + col0 + wn + ni * 8 + cl;
            size_t rB = rA + 8 * 1024;
            float v0 = acc[mi][ni][0], v1 = acc[mi][ni][1];
            float v2 = acc[mi][ni][2], v3 = acc[mi][ni][3];
            if (Addh) {
                uint32_t qh = *(const uint32_t*)(Addh + rA), ql = *(const uint32_t*)(Addl + rA);
                v0 += bf_lo(qh) + bf_lo(ql);  v1 += bf_hi(qh) + bf_hi(ql);
                uint32_t rh = *(const uint32_t*)(Addh + rB), rlq = *(const uint32_t*)(Addl + rB);
                v2 += bf_lo(rh) + bf_lo(rlq); v3 += bf_hi(rh) + bf_hi(rlq);
            }
            __nv_bfloat16 h0, l0, h1, l1;
            split_bf16(v0, h0, l0); split_bf16(v1, h1, l1);
            *(uint32_t*)(Ch + rA) = pack2(h0, h1);
            *(uint32_t*)(Cl + rA) = pack2(l0, l1);
            split_bf16(v2, h0, l0); split_bf16(v3, h1, l1);
            *(uint32_t*)(Ch + rB) = pack2(h0, h1);
            *(uint32_t*)(Cl + rB) = pack2(l0, l1);
        }
    }
}

// ---------------- G[b,l,t] = sum_d C[b,l,d] * B[b,t,d] ----------------
__global__ void __launch_bounds__(256) k_gmat(const float* __restrict__ Cm,
                                              const float* __restrict__ Bm) {
    __shared__ float Cs[64][65];
    __shared__ float Bs2[64][65];
    int b = blockIdx.z;
    int t0 = blockIdx.x * 64, l0 = blockIdx.y * 64;
    int tid = threadIdx.x;
    #pragma unroll
    for (int q = 0; q < 4; q++) {
        int idx = tid + q * 256;
        int r = idx >> 4, c4 = (idx & 15) * 4;
        float4 v = *(const float4*)(Cm + ((size_t)(b * LG + l0 + r)) * DS + c4);
        Cs[r][c4] = v.x; Cs[r][c4 + 1] = v.y; Cs[r][c4 + 2] = v.z; Cs[r][c4 + 3] = v.w;
        float4 w = *(const float4*)(Bm + ((size_t)(b * LG + t0 + r)) * DS + c4);
        Bs2[r][c4] = w.x; Bs2[r][c4 + 1] = w.y; Bs2[r][c4 + 2] = w.z; Bs2[r][c4 + 3] = w.w;
    }
    __syncthreads();
    int tx = tid & 15, ty = tid >> 4;
    float acc[4][4] = {};
    for (int d = 0; d < 64; d++) {
        float c[4], bb[4];
        #pragma unroll
        for (int i = 0; i < 4; i++) c[i] = Cs[ty * 4 + i][d];
        #pragma unroll
        for (int j = 0; j < 4; j++) bb[j] = Bs2[tx * 4 + j][d];
        #pragma unroll
        for (int i = 0; i < 4; i++)
            #pragma unroll
            for (int j = 0; j < 4; j++)
                acc[i][j] += c[i] * bb[j];
    }
    #pragma unroll
    for (int i = 0; i < 4; i++)
        #pragma unroll
        for (int j = 0; j < 4; j++)
            g_G[((size_t)b * LG + l0 + ty * 4 + i) * LG + t0 + tx * 4 + j] = acc[i][j];
}

// ---------------- y = ((Lmat . G) * dt_self_t) @ x_head + x ----------------
__global__ void __launch_bounds__(256) k_final(const __nv_bfloat16* __restrict__ Oh,
                                               const __nv_bfloat16* __restrict__ Ol,
                                               const float* __restrict__ x,
                                               const float* __restrict__ Dp,
                                               float* __restrict__ out) {
    int bh = blockIdx.z;
    int b = bh >> 3, h = bh & 7;
    int l0 = blockIdx.x * 64;
    size_t boff = (size_t)bh << 20;
    const float* Gb = g_G + (size_t)b * LG * LG;

    __shared__ float Os[64][65];
    __shared__ float Gs[64][65];
    __shared__ float xs[64][17];
    __shared__ float ws[64];

    int tid = threadIdx.x;
    int l = tid & 63;
    int d0 = (tid >> 6) * 4;
    float acc[4] = {0.f, 0.f, 0.f, 0.f};

    for (int t0 = 0; t0 < LG; t0 += 64) {
        #pragma unroll
        for (int q = 0; q < 2; q++) {
            int idx = tid + q * 256;
            int r = idx >> 3, c8 = (idx & 7) * 8;
            uint4 qh = *(const uint4*)(Oh + boff + (size_t)(l0 + r) * LG + t0 + c8);
            uint4 ql = *(const uint4*)(Ol + boff + (size_t)(l0 + r) * LG + t0 + c8);
            const uint32_t* hh = (const uint32_t*)&qh;
            const uint32_t* ll = (const uint32_t*)&ql;
            #pragma unroll
            for (int p = 0; p < 4; p++) {
                Os[r][c8 + 2 * p]     = bf_lo(hh[p]) + bf_lo(ll[p]);
                Os[r][c8 + 2 * p + 1] = bf_hi(hh[p]) + bf_hi(ll[p]);
            }
        }
        #pragma unroll
        for (int q = 0; q < 4; q++) {
            int idx = tid + q * 256;
            int r = idx >> 4, c4 = (idx & 15) * 4;
            float4 g = *(const float4*)(Gb + (size_t)(l0 + r) * LG + t0 + c4);
            Gs[r][c4] = g.x; Gs[r][c4 + 1] = g.y; Gs[r][c4 + 2] = g.z; Gs[r][c4 + 3] = g.w;
        }
        {
            int t = tid >> 2, d4 = (tid & 3) * 4;
            float4 v = *(const float4*)(x + (size_t)(b * LG + t0 + t) * 128 + h * HD + d4);
            xs[t][d4] = v.x; xs[t][d4 + 1] = v.y; xs[t][d4 + 2] = v.z; xs[t][d4 + 3] = v.w;
        }
        if (tid < 64) ws[tid] = g_w[h * NN_NODES + b * LG + t0 + tid];
        __syncthreads();
        #pragma unroll 8
        for (int tt = 0; tt < 64; tt++) {
            float a = Os[l][tt] * Gs[l][tt] * ws[tt];
            #pragma unroll
            for (int j = 0; j < 4; j++) acc[j] += a * xs[tt][d0 + j];
        }
        __syncthreads();
    }

    float dh = Dp[h];
    int n = b * LG + l0 + l;
    #pragma unroll
    for (int j = 0; j < 4; j++) {
        float xv = x[(size_t)n * 128 + h * HD + d0 + j];
        out[(size_t)n * 128 + (d0 + j) * NH + h] = acc[j] + xv * dh;
    }
}

// ---------------- host launcher ----------------
extern "C" void kernel_launch(void* const* d_in, const int* in_sizes, int n_in,
                              void* d_out, int out_size) {
    const float* x   = (const float*)d_in[0];
    const float* Bm  = (const float*)d_in[1];
    const float* Cm  = (const float*)d_in[2];
    const float* dt  = (const float*)d_in[3];
    const float* dtb = (const float*)d_in[4];
    const float* Dp  = (const float*)d_in[5];
    const int*   ei  = (const int*)  d_in[6];
    float* out = (float*)d_out;

    float* S;
    cudaGetSymbolAddress((void**)&S, g_S);
    __nv_bfloat16 *lah, *lal, *lath, *latl, *lbh, *lbl, *lbth, *lbtl, *oah, *oal, *obh, *obl;
    cudaGetSymbolAddress((void**)&lah,  g_La_h);  cudaGetSymbolAddress((void**)&lal,  g_La_l);
    cudaGetSymbolAddress((void**)&lath, g_LaT_h); cudaGetSymbolAddress((void**)&latl, g_LaT_l);
    cudaGetSymbolAddress((void**)&lbh,  g_Lb_h);  cudaGetSymbolAddress((void**)&lbl,  g_Lb_l);
    cudaGetSymbolAddress((void**)&lbth, g_LbT_h); cudaGetSymbolAddress((void**)&lbtl, g_LbT_l);
    cudaGetSymbolAddress((void**)&oah,  g_Oa_h);  cudaGetSymbolAddress((void**)&oal,  g_Oa_l);
    cudaGetSymbolAddress((void**)&obh,  g_Ob_h);  cudaGetSymbolAddress((void**)&obl,  g_Ob_l);

    cudaFuncSetAttribute(k_mma, cudaFuncAttributeMaxDynamicSharedMemorySize, MMA_SMEM);

    k_zero<<<2048, 256>>>(S, 64ULL << 20);
    k_node<<<(NN_NODES * NH + 255) / 256, 256>>>(dt, dtb);
    k_scatter<<<(NE * NH) / 256, 256>>>(ei);
    k_norm<<<(NB * LG) / 8, 256>>>();
    k_prep<<<dim3(32, 32, NB), dim3(32, 8)>>>();

    dim3 mg(8, 8, NB), mbk(256);
    dim3 tg(16, 16, NB);
    for (int it = 0; it < 5; it++) {
        // Lb = La @ La    (B-operand supplied as LaT, K-major)
        k_mma<<<mg, mbk, MMA_SMEM>>>(lah, lal, lath, latl, lbh, lbl, nullptr, nullptr);
        // LbT = Lb^T
        k_tp<<<tg, 256>>>(lbh, lbl, lbth, lbtl);
        // Ob = Oa @ Lb + Oa   (B-operand = LbT)
        k_mma<<<mg, mbk, MMA_SMEM>>>(oah, oal, lbth, lbtl, obh, obl, oah, oal);
        __nv_bfloat16* t;
        t = lah;  lah  = lbh;  lbh  = t;
        t = lal;  lal  = lbl;  lbl  = t;
        t = lath; lath = lbth; lbth = t;
        t = latl; latl = lbtl; lbtl = t;
        t = oah;  oah  = obh;  obh  = t;
        t = oal;  oal  = obl;  obl  = t;
    }

    k_gmat<<<dim3(16, 16, NG), 256>>>(Cm, Bm);
    k_final<<<dim3(16, 1, NB), 256>>>(oah, oal, x, Dp, out);
}